// round 14
// baseline (speedup 1.0000x reference)
#include <cuda_runtime.h>
#include <cuda_bf16.h>
#include <cuda_fp16.h>
#include <cstdint>

#define NN 50000
#define EE 800000
#define DD 128
#define TILES ((NN + 127) / 128)       // 391
#define PADROWS (TILES * 128)          // 50048
#define CSR_BLOCKS ((EE + 255) / 256)  // 3125
#define SCALE_BLOCKS ((NN * 32 + 255) / 256)
#define DEGPAD 53248                   // 256 * 208, int4-aligned scan reach
#define ZOFF ((unsigned)(NN << 8))     // byte offset of guaranteed-zero row
#define GEMM_GRID 296                  // 2 resident blocks x 148 SMs

// ---------------- scratch (static device globals; no allocation) ----------
// INVARIANT: g_deg[0..NN), g_cur[0..NN), g_done are zero at entry of every
// kernel_launch (zero-init at load; re-zeroed each call before reuse).
// Row NN of g_y16/g_h16 is never written -> always zero (gather pad target).
__device__ __half   g_y16[(NN + 1) * DD];  // y0 = dinv .* x   (fp16)
__device__ __half   g_h16[(NN + 1) * DD];  // y1 = dinv .* relu(layer0) (fp16)
__device__ uint32_t g_ap[PADROWS * DD];    // agg out, packed bf16 (hi,lo)
__device__ int      g_csr_src[EE];         // PRE-SHIFTED: src_row << 8
__device__ int      g_deg[DEGPAD];
__device__ int      g_off[NN + 1];
__device__ int      g_cur[NN];
__device__ float    g_dinv[NN];
__device__ int      g_is64;
__device__ int      g_done;
// W packed in mma B-fragment order, combined: uint4 = {hi0, hi1, lo0, lo1}
__device__ uint4    g_bp[2 * 8 * 16 * 32];

// ------------- K1: detect + W pack + degree count + last-block scan --------
__global__ void k_pre_deg(const int* __restrict__ raw,
                          const float* __restrict__ W) {
    __shared__ int found;
    __shared__ int isLast;
    if (threadIdx.x == 0) found = 0;
    __syncthreads();
    if (threadIdx.x < 128) {
        if (raw[2 * threadIdx.x + 1] != 0) found = 1;  // benign race
    }
    __syncthreads();
    int is64 = found ? 0 : 1;
    if (blockIdx.x == 0 && threadIdx.x == 0) g_is64 = is64;

    int idx = blockIdx.x * blockDim.x + threadIdx.x;
    if (idx < 2 * DD * DD) {
        int l = idx >> 14;
        int r = idx & 16383;
        int k = r >> 7;    // K index (in-dim)
        int n = r & 127;   // N index (out-dim)
        float v = W[l * DD * DD + k * DD + n];
        __nv_bfloat16 h  = __float2bfloat16(v);
        __nv_bfloat16 lo = __float2bfloat16(v - __bfloat162float(h));
        int ks = k >> 4, kk = k & 15;
        int reg = kk >> 3, k8 = kk & 7;
        int lane = ((n & 7) << 2) | (k8 >> 1);
        int i    = k8 & 1;
        int nt   = n >> 3;
        size_t idx4 = ((((size_t)l * 8 + ks) * 16 + nt) * 32) + lane;
        unsigned short* bp16 = (unsigned short*)g_bp;
        bp16[idx4 * 8 + reg * 2 + i]     = __bfloat16_as_ushort(h);
        bp16[idx4 * 8 + 4 + reg * 2 + i] = __bfloat16_as_ushort(lo);
    }
    if (idx < EE) {
        int d;
        if (is64) d = (int)((const long long*)raw)[EE + idx];
        else      d = ((const int*)raw)[EE + idx];
        atomicAdd(&g_deg[d], 1);
    }

    // ---- last-block inline scan -> g_off + g_dinv ----
    __threadfence();
    __syncthreads();
    if (threadIdx.x == 0) {
        int tk = atomicAdd(&g_done, 1);
        isLast = (tk == (int)gridDim.x - 1);
    }
    __syncthreads();
    if (!isLast) return;

    __shared__ int ssum[256];
    int t = threadIdx.x;
    const int4* dp = (const int4*)(g_deg + t * 208);
    int sum = 0;
    #pragma unroll 4
    for (int j = 0; j < 52; ++j) {
        int4 v = dp[j];
        sum += v.x + v.y + v.z + v.w;
    }
    ssum[t] = sum;
    __syncthreads();
    for (int d = 1; d < 256; d <<= 1) {
        int v = (t >= d) ? ssum[t - d] : 0;
        __syncthreads();
        ssum[t] += v;
        __syncthreads();
    }
    int run = ssum[t] - sum;
    int base = t * 208;
    if (base < NN) {
        #pragma unroll 4
        for (int j = 0; j < 52; ++j) {
            int4 v = dp[j];
            int ix = base + j * 4;
            if (ix + 0 < NN) { g_off[ix+0] = run; g_dinv[ix+0] = rsqrtf((float)v.x + 1.0f); run += v.x; }
            if (ix + 1 < NN) { g_off[ix+1] = run; g_dinv[ix+1] = rsqrtf((float)v.y + 1.0f); run += v.y; }
            if (ix + 2 < NN) { g_off[ix+2] = run; g_dinv[ix+2] = rsqrtf((float)v.z + 1.0f); run += v.z; }
            if (ix + 3 < NN) { g_off[ix+3] = run; g_dinv[ix+3] = rsqrtf((float)v.w + 1.0f); run += v.w; }
        }
    }
    if (t == 255) g_off[NN] = ssum[255];
    if (t == 0)   g_done = 0;   // restore zero-invariant for next replay
}

// ------------- K2: CSR scatter (pre-shifted src) + y0 = fp16(dinv.*x) ------
__global__ void k_csr_scale(const void* __restrict__ raw,
                            const float* __restrict__ x) {
    int b = blockIdx.x;
    if (b < CSR_BLOCKS) {
        int e = b * 256 + threadIdx.x;
        if (e < EE) {
            int s, d;
            if (g_is64) {
                const long long* p = (const long long*)raw;
                s = (int)p[e];
                d = (int)p[EE + e];
            } else {
                const int* p = (const int*)raw;
                s = p[e];
                d = p[EE + e];
            }
            int pidx = g_off[d] + atomicAdd(&g_cur[d], 1);
            g_csr_src[pidx] = s << 8;   // byte offset of fp16 row
        }
    } else {
        int i = (b - CSR_BLOCKS) * 256 + threadIdx.x;
        if (i < NN * 32) {
            int row = i >> 5, l = i & 31;
            float di = g_dinv[row];
            float4 v = ((const float4*)(x + (size_t)row * DD))[l];
            __half2 h01 = __floats2half2_rn(v.x * di, v.y * di);
            __half2 h23 = __floats2half2_rn(v.z * di, v.w * di);
            uint2 o;
            o.x = *(uint32_t*)&h01;
            o.y = *(uint32_t*)&h23;
            *(uint2*)(g_y16 + (size_t)row * DD + 4 * l) = o;
        }
    }
}

// ------------- K3/K5: aggregation, 2 nodes/warp (R11 version) --------------
__device__ __forceinline__ void tree2(const uint4* vv, float* acc) {
    #pragma unroll
    for (int s = 0; s < 4; ++s) {
        const uint32_t* u = (const uint32_t*)vv;   // stride 4 per edge
        __half2 a01 = __hadd2(*(__half2*)&u[0*4+s], *(__half2*)&u[1*4+s]);
        __half2 a23 = __hadd2(*(__half2*)&u[2*4+s], *(__half2*)&u[3*4+s]);
        __half2 as  = __hadd2(a01, a23);
        float2 f = __half22float2(as);
        acc[2*s]   += f.x;
        acc[2*s+1] += f.y;
    }
}

__global__ void __launch_bounds__(256)
k_agg(int use_internal) {
    if (!use_internal) {
        int zi = blockIdx.x * 256 + threadIdx.x;
        if (zi < NN) { g_deg[zi] = 0; g_cur[zi] = 0; }
    }
    int w    = (blockIdx.x * blockDim.x + threadIdx.x) >> 5;
    int lane = threadIdx.x & 31;
    int n0 = w * 2;
    if (n0 >= NN) return;
    int half = lane >> 4;
    int hl   = lane & 15;
    int node = n0 + half;
    const char* __restrict__ yb =
        (const char*)(use_internal ? g_h16 : g_y16) + 16 * hl;

    int b0  = g_off[n0];
    int mid = g_off[n0 + 1];
    int e1  = g_off[n0 + 2];
    int m0 = mid - b0, m1 = e1 - mid;
    int mybeg = half ? mid : b0;
    int m     = half ? m1 : m0;
    int mmax  = m0 > m1 ? m0 : m1;

    float acc[8];
    {
        uint4 v = *(const uint4*)(yb + ((size_t)node << 8));
        const uint32_t* u = (const uint32_t*)&v;
        #pragma unroll
        for (int s = 0; s < 4; ++s) {
            float2 f = __half22float2(*(__half2*)&u[s]);
            acc[2*s] = f.x; acc[2*s+1] = f.y;
        }
    }

    for (int e0 = 0; e0 < mmax; e0 += 16) {
        int idx = e0 + hl;
        unsigned off = (idx < m) ? (unsigned)g_csr_src[mybeg + idx] : ZOFF;
        #pragma unroll
        for (int t = 0; t < 4; ++t) {
            if (e0 + t * 4 < mmax) {
                uint4 vv[4];
                #pragma unroll
                for (int j = 0; j < 4; ++j) {
                    unsigned o = __shfl_sync(0xffffffffu, off, t * 4 + j, 16);
                    vv[j] = *(const uint4*)(yb + o);
                }
                tree2(vv, acc);
            }
        }
    }

    float di = g_dinv[node];
    #pragma unroll
    for (int s = 0; s < 8; ++s) acc[s] *= di;

    uint32_t o8[8];
    #pragma unroll
    for (int t = 0; t < 4; ++t) {
        float a = acc[2*t], b = acc[2*t+1];
        __nv_bfloat162 h = __floats2bfloat162_rn(a, b);
        float ra = a - __bfloat162float(__low2bfloat16(h));
        float rb = b - __bfloat162float(__high2bfloat16(h));
        __nv_bfloat162 l = __floats2bfloat162_rn(ra, rb);
        o8[2*t]   = *(uint32_t*)&h;
        o8[2*t+1] = *(uint32_t*)&l;
    }
    uint32_t* dst = g_ap + (size_t)node * DD + 8 * hl;
    *(uint4*)(dst)     = make_uint4(o8[0], o8[1], o8[2], o8[3]);
    *(uint4*)(dst + 4) = make_uint4(o8[4], o8[5], o8[6], o8[7]);
}

// ------------- K4/K6: mma.sync GEMM, persistent tile loop (R11) ------------
__device__ __forceinline__ void mma16816(float* d, const uint32_t* a,
                                         const uint32_t b0, const uint32_t b1) {
    asm volatile(
        "mma.sync.aligned.m16n8k16.row.col.f32.bf16.bf16.f32 "
        "{%0,%1,%2,%3}, {%4,%5,%6,%7}, {%8,%9}, {%0,%1,%2,%3};"
        : "+f"(d[0]), "+f"(d[1]), "+f"(d[2]), "+f"(d[3])
        : "r"(a[0]), "r"(a[1]), "r"(a[2]), "r"(a[3]), "r"(b0), "r"(b1));
}

__global__ void __launch_bounds__(256)
k_gemm_mma(const float* __restrict__ bg, float* __restrict__ outext,
           int layer, int write_internal) {
    int tid  = threadIdx.x;
    int lane = tid & 31;
    int wid  = tid >> 5;
    int qrow = lane >> 2;
    int qcol = (lane & 3) * 2;
    int q    = lane & 3;

    const uint2* __restrict__ ap  = (const uint2*)g_ap;
    const uint4* __restrict__ bp4 = (const uint4*)g_bp;

    for (int tile = blockIdx.x; tile < TILES; tile += GEMM_GRID) {
        int mbase = tile * 128 + (wid & 3) * 32;
        int nbase = (wid >> 2) * 64;

        float acc[2][8][4];
        #pragma unroll
        for (int mt = 0; mt < 2; ++mt)
            #pragma unroll
            for (int nt = 0; nt < 8; ++nt)
                #pragma unroll
                for (int j = 0; j < 4; ++j) acc[mt][nt][j] = 0.0f;

        #pragma unroll 2
        for (int ks = 0; ks < 8; ++ks) {
            uint32_t ahi[2][4], alo[2][4];
            #pragma unroll
            for (int mt = 0; mt < 2; ++mt) {
                int r0 = mbase + mt * 16 + qrow;
                int r1 = r0 + 8;
                uint2 v00 = ap[(size_t)r0 * 64 + ks * 8 + q];
                uint2 v10 = ap[(size_t)r1 * 64 + ks * 8 + q];
                uint2 v01 = ap[(size_t)r0 * 64 + ks * 8 + 4 + q];
                uint2 v11 = ap[(size_t)r1 * 64 + ks * 8 + 4 + q];
                ahi[mt][0] = v00.x; alo[mt][0] = v00.y;
                ahi[mt][1] = v10.x; alo[mt][1] = v10.y;
                ahi[mt][2] = v01.x; alo[mt][2] = v01.y;
                ahi[mt][3] = v11.x; alo[mt][3] = v11.y;
            }
            int bbase = (((layer * 8 + ks) * 16 + (nbase >> 3)) * 32) + lane;
            uint4 bv[8];
            #pragma unroll
            for (int nt = 0; nt < 8; ++nt) bv[nt] = bp4[bbase + nt * 32];
            #pragma unroll
            for (int mt = 0; mt < 2; ++mt)
                #pragma unroll
                for (int nt = 0; nt < 8; ++nt) {
                    mma16816(acc[mt][nt], ahi[mt], bv[nt].x, bv[nt].y);
                    mma16816(acc[mt][nt], alo[mt], bv[nt].x, bv[nt].y);
                    mma16816(acc[mt][nt], ahi[mt], bv[nt].z, bv[nt].w);
                }
        }

        if (write_internal) {
            float dv[2][2];
            #pragma unroll
            for (int mt = 0; mt < 2; ++mt) {
                int r0 = mbase + mt * 16 + qrow;
                int r1 = r0 + 8;
                dv[mt][0] = (r0 < NN) ? g_dinv[r0] : 0.0f;
                dv[mt][1] = (r1 < NN) ? g_dinv[r1] : 0.0f;
            }
            #pragma unroll
            for (int nt = 0; nt < 8; ++nt) {
                int col = (wid >> 2) * 64 + nt * 8 + qcol;
                float2 bb = *(const float2*)(bg + col);
                #pragma unroll
                for (int mt = 0; mt < 2; ++mt) {
                    int r0 = mbase + mt * 16 + qrow;
                    int r1 = r0 + 8;
                    if (r0 < NN) {
                        __half2 o = __floats2half2_rn(
                            fmaxf(acc[mt][nt][0] + bb.x, 0.0f) * dv[mt][0],
                            fmaxf(acc[mt][nt][1] + bb.y, 0.0f) * dv[mt][0]);
                        *(__half2*)(g_h16 + (size_t)r0 * DD + col) = o;
                    }
                    if (r1 < NN) {
                        __half2 o = __floats2half2_rn(
                            fmaxf(acc[mt][nt][2] + bb.x, 0.0f) * dv[mt][1],
                            fmaxf(acc[mt][nt][3] + bb.y, 0.0f) * dv[mt][1]);
                        *(__half2*)(g_h16 + (size_t)r1 * DD + col) = o;
                    }
                }
            }
        } else {
            #pragma unroll
            for (int nt = 0; nt < 8; ++nt) {
                int col = (wid >> 2) * 64 + nt * 8 + qcol;
                float2 bb = *(const float2*)(bg + col);
                #pragma unroll
                for (int mt = 0; mt < 2; ++mt) {
                    int r0 = mbase + mt * 16 + qrow;
                    int r1 = r0 + 8;
                    if (r0 < NN) {
                        float2 o0;
                        o0.x = fmaxf(acc[mt][nt][0] + bb.x, 0.0f);
                        o0.y = fmaxf(acc[mt][nt][1] + bb.y, 0.0f);
                        *(float2*)(outext + (size_t)r0 * DD + col) = o0;
                    }
                    if (r1 < NN) {
                        float2 o1;
                        o1.x = fmaxf(acc[mt][nt][2] + bb.x, 0.0f);
                        o1.y = fmaxf(acc[mt][nt][3] + bb.y, 0.0f);
                        *(float2*)(outext + (size_t)r1 * DD + col) = o1;
                    }
                }
            }
        }
    }
}

// ---------------- launch ----------------------------------------------------
extern "C" void kernel_launch(void* const* d_in, const int* in_sizes, int n_in,
                              void* d_out, int out_size) {
    const float* x  = (const float*)d_in[0];
    const void*  ei = d_in[1];
    const float* W  = (const float*)d_in[2];
    const float* b  = (const float*)d_in[3];
    float* out = (float*)d_out;

    k_pre_deg<<<CSR_BLOCKS, 256>>>((const int*)ei, W);
    k_csr_scale<<<CSR_BLOCKS + SCALE_BLOCKS, 256>>>(ei, x);

    int aggGrid = (NN / 2 + 7) / 8;
    k_agg<<<aggGrid, 256>>>(0);
    k_gemm_mma<<<GEMM_GRID, 256>>>(b, out, 0, 1);
    k_agg<<<aggGrid, 256>>>(1);
    k_gemm_mma<<<GEMM_GRID, 256>>>(b + DD, out, 1, 0);
}

// round 15
// speedup vs baseline: 1.1772x; 1.1772x over previous
#include <cuda_runtime.h>
#include <cuda_bf16.h>
#include <cuda_fp16.h>
#include <cstdint>

#define NN 50000
#define EE 800000
#define DD 128
#define TILES ((NN + 127) / 128)       // 391
#define PADROWS (TILES * 128)          // 50048
#define CSR_BLOCKS ((EE + 255) / 256)  // 3125
#define SCALE_BLOCKS ((NN * 32 + 255) / 256)
#define DEGPAD 53248                   // 1024 * 52, int4-aligned scan reach
#define ZOFF ((unsigned)(NN << 8))     // byte offset of guaranteed-zero row

// ---------------- scratch (static device globals; no allocation) ----------
// INVARIANT: g_deg[0..NN) and g_cur[0..NN) are zero at entry of every
// kernel_launch (zero-init at load; re-zeroed by k_agg layer 0 each call).
// Row NN of g_y16/g_h16 is never written -> always zero (gather pad target).
__device__ __half   g_y16[(NN + 1) * DD];  // y0 = dinv .* x   (fp16)
__device__ __half   g_h16[(NN + 1) * DD];  // y1 = dinv .* relu(layer0) (fp16)
__device__ uint32_t g_ap[PADROWS * DD];    // agg out, packed bf16 (hi,lo)
__device__ int      g_csr_src[EE];         // PRE-SHIFTED: src_row << 8
__device__ int      g_deg[DEGPAD];
__device__ int      g_off[NN + 1];
__device__ int      g_cur[NN];
__device__ float    g_dinv[NN];
__device__ int      g_is64;
// W packed in mma B-fragment order, combined: uint4 = {hi0, hi1, lo0, lo1}
__device__ uint4    g_bp[2 * 8 * 16 * 32];

// ------------- K1: fused dtype-detect + W pack + degree count --------------
__global__ void k_pre_deg(const int* __restrict__ raw,
                          const float* __restrict__ W) {
    __shared__ int found;
    if (threadIdx.x == 0) found = 0;
    __syncthreads();
    if (threadIdx.x < 128) {
        if (raw[2 * threadIdx.x + 1] != 0) found = 1;  // benign race
    }
    __syncthreads();
    int is64 = found ? 0 : 1;
    if (blockIdx.x == 0 && threadIdx.x == 0) g_is64 = is64;

    int idx = blockIdx.x * blockDim.x + threadIdx.x;
    if (idx < 2 * DD * DD) {
        int l = idx >> 14;
        int r = idx & 16383;
        int k = r >> 7;    // K index (in-dim)
        int n = r & 127;   // N index (out-dim)
        float v = W[l * DD * DD + k * DD + n];
        __nv_bfloat16 h  = __float2bfloat16(v);
        __nv_bfloat16 lo = __float2bfloat16(v - __bfloat162float(h));
        int ks = k >> 4, kk = k & 15;
        int reg = kk >> 3, k8 = kk & 7;
        int lane = ((n & 7) << 2) | (k8 >> 1);
        int i    = k8 & 1;
        int nt   = n >> 3;
        size_t idx4 = ((((size_t)l * 8 + ks) * 16 + nt) * 32) + lane;
        unsigned short* bp16 = (unsigned short*)g_bp;
        bp16[idx4 * 8 + reg * 2 + i]     = __bfloat16_as_ushort(h);
        bp16[idx4 * 8 + 4 + reg * 2 + i] = __bfloat16_as_ushort(lo);
    }
    if (idx < EE) {
        int d;
        if (is64) d = (int)((const long long*)raw)[EE + idx];
        else      d = ((const int*)raw)[EE + idx];
        atomicAdd(&g_deg[d], 1);
    }
}

// ------------- K2: single-block scan (int4 loads) -> offsets + dinv --------
__global__ void k_scan() {
    const int T = 1024;
    const int ITEMS = 52;
    __shared__ int sm[T];
    int t = threadIdx.x;
    int base = t * ITEMS;

    const int4* dp = (const int4*)(g_deg + base);
    int sum = 0;
    #pragma unroll
    for (int j = 0; j < ITEMS / 4; ++j) {
        int4 v = dp[j];
        sum += v.x + v.y + v.z + v.w;
    }
    sm[t] = sum;
    __syncthreads();
    for (int dstep = 1; dstep < T; dstep <<= 1) {
        int v = (t >= dstep) ? sm[t - dstep] : 0;
        __syncthreads();
        sm[t] += v;
        __syncthreads();
    }
    int run = sm[t] - sum;
    if (base < NN) {
        #pragma unroll
        for (int j = 0; j < ITEMS / 4; ++j) {
            int4 v = dp[j];
            int idx = base + j * 4;
            if (idx + 0 < NN) { g_off[idx+0] = run; g_dinv[idx+0] = rsqrtf((float)v.x + 1.0f); run += v.x; }
            if (idx + 1 < NN) { g_off[idx+1] = run; g_dinv[idx+1] = rsqrtf((float)v.y + 1.0f); run += v.y; }
            if (idx + 2 < NN) { g_off[idx+2] = run; g_dinv[idx+2] = rsqrtf((float)v.z + 1.0f); run += v.z; }
            if (idx + 3 < NN) { g_off[idx+3] = run; g_dinv[idx+3] = rsqrtf((float)v.w + 1.0f); run += v.w; }
        }
    }
    if (t == T - 1) g_off[NN] = sm[T - 1];
}

// ------------- K3: CSR scatter (pre-shifted src) + y0 = fp16(dinv.*x) ------
__global__ void k_csr_scale(const void* __restrict__ raw,
                            const float* __restrict__ x) {
    int b = blockIdx.x;
    if (b < CSR_BLOCKS) {
        int e = b * 256 + threadIdx.x;
        if (e < EE) {
            int s, d;
            if (g_is64) {
                const long long* p = (const long long*)raw;
                s = (int)p[e];
                d = (int)p[EE + e];
            } else {
                const int* p = (const int*)raw;
                s = p[e];
                d = p[EE + e];
            }
            int pidx = g_off[d] + atomicAdd(&g_cur[d], 1);
            g_csr_src[pidx] = s << 8;   // byte offset of fp16 row
        }
    } else {
        int i = (b - CSR_BLOCKS) * 256 + threadIdx.x;
        if (i < NN * 32) {
            int row = i >> 5, l = i & 31;
            float di = g_dinv[row];
            float4 v = ((const float4*)(x + (size_t)row * DD))[l];
            __half2 h01 = __floats2half2_rn(v.x * di, v.y * di);
            __half2 h23 = __floats2half2_rn(v.z * di, v.w * di);
            uint2 o;
            o.x = *(uint32_t*)&h01;
            o.y = *(uint32_t*)&h23;
            *(uint2*)(g_y16 + (size_t)row * DD + 4 * l) = o;
        }
    }
}

// ------------- K4/K6: aggregation, 2 nodes/warp (R11 version) --------------
__device__ __forceinline__ void tree2(const uint4* vv, float* acc) {
    #pragma unroll
    for (int s = 0; s < 4; ++s) {
        const uint32_t* u = (const uint32_t*)vv;   // stride 4 per edge
        __half2 a01 = __hadd2(*(__half2*)&u[0*4+s], *(__half2*)&u[1*4+s]);
        __half2 a23 = __hadd2(*(__half2*)&u[2*4+s], *(__half2*)&u[3*4+s]);
        __half2 as  = __hadd2(a01, a23);
        float2 f = __half22float2(as);
        acc[2*s]   += f.x;
        acc[2*s+1] += f.y;
    }
}

__global__ void __launch_bounds__(256)
k_agg(int use_internal) {
    if (!use_internal) {
        int zi = blockIdx.x * 256 + threadIdx.x;
        if (zi < NN) { g_deg[zi] = 0; g_cur[zi] = 0; }
    }
    int w    = (blockIdx.x * blockDim.x + threadIdx.x) >> 5;
    int lane = threadIdx.x & 31;
    int n0 = w * 2;
    if (n0 >= NN) return;
    int half = lane >> 4;
    int hl   = lane & 15;
    int node = n0 + half;
    const char* __restrict__ yb =
        (const char*)(use_internal ? g_h16 : g_y16) + 16 * hl;

    int b0  = g_off[n0];
    int mid = g_off[n0 + 1];
    int e1  = g_off[n0 + 2];
    int m0 = mid - b0, m1 = e1 - mid;
    int mybeg = half ? mid : b0;
    int m     = half ? m1 : m0;
    int mmax  = m0 > m1 ? m0 : m1;

    float acc[8];
    {
        uint4 v = *(const uint4*)(yb + ((size_t)node << 8));
        const uint32_t* u = (const uint32_t*)&v;
        #pragma unroll
        for (int s = 0; s < 4; ++s) {
            float2 f = __half22float2(*(__half2*)&u[s]);
            acc[2*s] = f.x; acc[2*s+1] = f.y;
        }
    }

    for (int e0 = 0; e0 < mmax; e0 += 16) {
        int idx = e0 + hl;
        unsigned off = (idx < m) ? (unsigned)g_csr_src[mybeg + idx] : ZOFF;
        #pragma unroll
        for (int t = 0; t < 4; ++t) {
            if (e0 + t * 4 < mmax) {
                uint4 vv[4];
                #pragma unroll
                for (int j = 0; j < 4; ++j) {
                    unsigned o = __shfl_sync(0xffffffffu, off, t * 4 + j, 16);
                    vv[j] = *(const uint4*)(yb + o);
                }
                tree2(vv, acc);
            }
        }
    }

    float di = g_dinv[node];
    #pragma unroll
    for (int s = 0; s < 8; ++s) acc[s] *= di;

    uint32_t o8[8];
    #pragma unroll
    for (int t = 0; t < 4; ++t) {
        float a = acc[2*t], b = acc[2*t+1];
        __nv_bfloat162 h = __floats2bfloat162_rn(a, b);
        float ra = a - __bfloat162float(__low2bfloat16(h));
        float rb = b - __bfloat162float(__high2bfloat16(h));
        __nv_bfloat162 l = __floats2bfloat162_rn(ra, rb);
        o8[2*t]   = *(uint32_t*)&h;
        o8[2*t+1] = *(uint32_t*)&l;
    }
    uint32_t* dst = g_ap + (size_t)node * DD + 8 * hl;
    *(uint4*)(dst)     = make_uint4(o8[0], o8[1], o8[2], o8[3]);
    *(uint4*)(dst + 4) = make_uint4(o8[4], o8[5], o8[6], o8[7]);
}

// ------------- K5/K7: mma GEMM, 16 rows x 64 cols per warp -----------------
// Block: 8 warps -> 128 rows x 64 cols. Grid (TILES, 2): blockIdx.y = n-slice.
__device__ __forceinline__ void mma16816(float* d, const uint32_t* a,
                                         const uint32_t b0, const uint32_t b1) {
    asm volatile(
        "mma.sync.aligned.m16n8k16.row.col.f32.bf16.bf16.f32 "
        "{%0,%1,%2,%3}, {%4,%5,%6,%7}, {%8,%9}, {%0,%1,%2,%3};"
        : "+f"(d[0]), "+f"(d[1]), "+f"(d[2]), "+f"(d[3])
        : "r"(a[0]), "r"(a[1]), "r"(a[2]), "r"(a[3]), "r"(b0), "r"(b1));
}

__global__ void __launch_bounds__(256, 3)
k_gemm_mma(const float* __restrict__ bg, float* __restrict__ outext,
           int layer, int write_internal) {
    int tid  = threadIdx.x;
    int lane = tid & 31;
    int wid  = tid >> 5;
    int qrow = lane >> 2;
    int qcol = (lane & 3) * 2;
    int q    = lane & 3;

    int mbase = blockIdx.x * 128 + wid * 16;   // warp's 16 rows
    int nbase = blockIdx.y * 64;               // block's 64-col slice

    const uint2* __restrict__ ap  = (const uint2*)g_ap;
    const uint4* __restrict__ bp4 = (const uint4*)g_bp;

    float acc[8][4];
    #pragma unroll
    for (int nt = 0; nt < 8; ++nt)
        #pragma unroll
        for (int j = 0; j < 4; ++j) acc[nt][j] = 0.0f;

    int r0 = mbase + qrow;
    int r1 = r0 + 8;

    #pragma unroll 2
    for (int ks = 0; ks < 8; ++ks) {
        uint2 v00 = ap[(size_t)r0 * 64 + ks * 8 + q];
        uint2 v10 = ap[(size_t)r1 * 64 + ks * 8 + q];
        uint2 v01 = ap[(size_t)r0 * 64 + ks * 8 + 4 + q];
        uint2 v11 = ap[(size_t)r1 * 64 + ks * 8 + 4 + q];
        uint32_t ahi[4], alo[4];
        ahi[0] = v00.x; alo[0] = v00.y;
        ahi[1] = v10.x; alo[1] = v10.y;
        ahi[2] = v01.x; alo[2] = v01.y;
        ahi[3] = v11.x; alo[3] = v11.y;

        int bbase = (((layer * 8 + ks) * 16 + (nbase >> 3)) * 32) + lane;
        #pragma unroll
        for (int nt = 0; nt < 8; ++nt) {
            uint4 bv = bp4[bbase + nt * 32];
            mma16816(acc[nt], ahi, bv.x, bv.y);
            mma16816(acc[nt], alo, bv.x, bv.y);
            mma16816(acc[nt], ahi, bv.z, bv.w);
        }
    }

    if (write_internal) {
        float d0 = (r0 < NN) ? g_dinv[r0] : 0.0f;
        float d1 = (r1 < NN) ? g_dinv[r1] : 0.0f;
        #pragma unroll
        for (int nt = 0; nt < 8; ++nt) {
            int col = nbase + nt * 8 + qcol;
            float2 bb = *(const float2*)(bg + col);
            if (r0 < NN) {
                __half2 o = __floats2half2_rn(
                    fmaxf(acc[nt][0] + bb.x, 0.0f) * d0,
                    fmaxf(acc[nt][1] + bb.y, 0.0f) * d0);
                *(__half2*)(g_h16 + (size_t)r0 * DD + col) = o;
            }
            if (r1 < NN) {
                __half2 o = __floats2half2_rn(
                    fmaxf(acc[nt][2] + bb.x, 0.0f) * d1,
                    fmaxf(acc[nt][3] + bb.y, 0.0f) * d1);
                *(__half2*)(g_h16 + (size_t)r1 * DD + col) = o;
            }
        }
    } else {
        #pragma unroll
        for (int nt = 0; nt < 8; ++nt) {
            int col = nbase + nt * 8 + qcol;
            float2 bb = *(const float2*)(bg + col);
            if (r0 < NN) {
                float2 o0;
                o0.x = fmaxf(acc[nt][0] + bb.x, 0.0f);
                o0.y = fmaxf(acc[nt][1] + bb.y, 0.0f);
                *(float2*)(outext + (size_t)r0 * DD + col) = o0;
            }
            if (r1 < NN) {
                float2 o1;
                o1.x = fmaxf(acc[nt][2] + bb.x, 0.0f);
                o1.y = fmaxf(acc[nt][3] + bb.y, 0.0f);
                *(float2*)(outext + (size_t)r1 * DD + col) = o1;
            }
        }
    }
}

// ---------------- launch ----------------------------------------------------
extern "C" void kernel_launch(void* const* d_in, const int* in_sizes, int n_in,
                              void* d_out, int out_size) {
    const float* x  = (const float*)d_in[0];
    const void*  ei = d_in[1];
    const float* W  = (const float*)d_in[2];
    const float* b  = (const float*)d_in[3];
    float* out = (float*)d_out;

    k_pre_deg<<<CSR_BLOCKS, 256>>>((const int*)ei, W);
    k_scan<<<1, 1024>>>();
    k_csr_scale<<<CSR_BLOCKS + SCALE_BLOCKS, 256>>>(ei, x);

    int aggGrid = (NN / 2 + 7) / 8;
    dim3 gemmGrid(TILES, 2);
    k_agg<<<aggGrid, 256>>>(0);
    k_gemm_mma<<<gemmGrid, 256>>>(b, out, 0, 1);
    k_agg<<<aggGrid, 256>>>(1);
    k_gemm_mma<<<gemmGrid, 256>>>(b + DD, out, 1, 0);
}